// round 1
// baseline (speedup 1.0000x reference)
#include <cuda_runtime.h>
#include <math.h>

// Problem dims (fixed for this dataset)
#define NTOK 16384        // B*T = 8*2048
#define DDIM 1024
#define NEXP 8
#define FDIM 4096
#define TOPK 2
#define NK   (NTOK*TOPK)  // 32768 assignments
#define CAP  2560         // int(1.25 * 16384 / 8)

// ---------------- scratch (device globals: allocation-free) ----------------
__device__ float g_buf[(size_t)NEXP * CAP * DDIM];   // dispatched tokens  [E,cap,D]   80 MB
__device__ float g_h  [(size_t)NEXP * CAP * FDIM];   // hidden activations [E,cap,F]  320 MB
__device__ float g_o  [(size_t)NEXP * CAP * DDIM];   // expert outputs     [E,cap,D]   80 MB
__device__ int   g_exp [NK];                         // expert id per assignment
__device__ float g_gate[NK];                         // gate value per assignment
__device__ int   g_pos [NK];                         // arrival position within expert

// ---------------- router: warp per token -----------------------------------
__global__ void router_kernel(const float* __restrict__ x,
                              const float* __restrict__ wr,
                              const float* __restrict__ br) {
    int tok  = (blockIdx.x * blockDim.x + threadIdx.x) >> 5;
    int lane = threadIdx.x & 31;
    if (tok >= NTOK) return;
    const float* xr = x + (size_t)tok * DDIM;

    float acc[NEXP];
#pragma unroll
    for (int e = 0; e < NEXP; e++) acc[e] = 0.f;

    for (int c = lane * 4; c < DDIM; c += 128) {
        float4 xv = *(const float4*)(xr + c);
        float xs[4] = {xv.x, xv.y, xv.z, xv.w};
#pragma unroll
        for (int j = 0; j < 4; j++) {
            const float4* w = (const float4*)(wr + (size_t)(c + j) * NEXP);
            float4 w0 = w[0], w1 = w[1];
            acc[0] += xs[j] * w0.x; acc[1] += xs[j] * w0.y;
            acc[2] += xs[j] * w0.z; acc[3] += xs[j] * w0.w;
            acc[4] += xs[j] * w1.x; acc[5] += xs[j] * w1.y;
            acc[6] += xs[j] * w1.z; acc[7] += xs[j] * w1.w;
        }
    }
#pragma unroll
    for (int off = 16; off; off >>= 1) {
#pragma unroll
        for (int e = 0; e < NEXP; e++)
            acc[e] += __shfl_xor_sync(0xffffffffu, acc[e], off);
    }
    if (lane == 0) {
        float l[NEXP], mx = -1e30f;
#pragma unroll
        for (int e = 0; e < NEXP; e++) { l[e] = acc[e] + br[e]; mx = fmaxf(mx, l[e]); }
        float s = 0.f;
#pragma unroll
        for (int e = 0; e < NEXP; e++) { l[e] = expf(l[e] - mx); s += l[e]; }
        float inv = 1.f / s;
#pragma unroll
        for (int e = 0; e < NEXP; e++) l[e] *= inv;
        // top-2, ties -> lowest index (matches jax.lax.top_k)
        int i0 = 0; float v0 = l[0];
#pragma unroll
        for (int e = 1; e < NEXP; e++) if (l[e] > v0) { v0 = l[e]; i0 = e; }
        int i1 = -1; float v1 = -1.f;
#pragma unroll
        for (int e = 0; e < NEXP; e++) if (e != i0 && l[e] > v1) { v1 = l[e]; i1 = e; }
        g_exp [tok * 2]     = i0;  g_exp [tok * 2 + 1] = i1;
        g_gate[tok * 2]     = v0;  g_gate[tok * 2 + 1] = v1;
    }
}

// ---------------- exact arrival-order positions (single block) -------------
__global__ void scan_kernel() {
    __shared__ int s[NEXP][1024];
    const int t = threadIdx.x;
    const int base = t * 32;

    int cnt[NEXP];
#pragma unroll
    for (int e = 0; e < NEXP; e++) cnt[e] = 0;

    int le[32];
#pragma unroll
    for (int i = 0; i < 32; i++) { int e = g_exp[base + i]; le[i] = e; cnt[e]++; }

#pragma unroll
    for (int e = 0; e < NEXP; e++) s[e][t] = cnt[e];
    __syncthreads();

    // inclusive Hillis-Steele scan over 1024 threads, all 8 experts at once
    for (int st = 1; st < 1024; st <<= 1) {
        int v[NEXP];
#pragma unroll
        for (int e = 0; e < NEXP; e++)
            v[e] = s[e][t] + (t >= st ? s[e][t - st] : 0);
        __syncthreads();
#pragma unroll
        for (int e = 0; e < NEXP; e++) s[e][t] = v[e];
        __syncthreads();
    }

    int run[NEXP];
#pragma unroll
    for (int e = 0; e < NEXP; e++) run[e] = (t > 0) ? s[e][t - 1] : 0;

#pragma unroll
    for (int i = 0; i < 32; i++) {
        int e = le[i];
        g_pos[base + i] = run[e]++;
    }
}

// ---------------- dispatch: one block per assignment ------------------------
__global__ void dispatch_kernel(const float* __restrict__ x) {
    const int a = blockIdx.x;
    const int p = g_pos[a];
    if (p >= CAP) return;                       // dropped by capacity
    const int e   = g_exp[a];
    const int tok = a >> 1;
    const float4* src = (const float4*)(x + (size_t)tok * DDIM);
    float4*       dst = (float4*)(g_buf + ((size_t)e * CAP + p) * DDIM);
    dst[threadIdx.x] = src[threadIdx.x];        // 256 thr * float4 = 1024 floats
}

// ---------------- grouped SGEMM 128x128x8, double-buffered -----------------
__device__ __forceinline__ float gelu_exact(float v) {
    return 0.5f * v * (1.f + erff(v * 0.70710678118654752440f));
}

// GELU=true:  C = gelu(g_buf @ B + bias) -> g_h    (KD=1024, ND=4096)
// GELU=false: C = g_h  @ B + bias        -> g_o    (KD=4096, ND=1024)
template<int KD, int ND, bool GELU>
__global__ void __launch_bounds__(256, 2)
gemm_kernel(const float* __restrict__ Ball, const float* __restrict__ biasAll) {
    __shared__ float As[2][8][128];
    __shared__ float Bs[2][8][128];

    const int ex = blockIdx.z;
    const float* A    = (GELU ? g_buf : g_h) + (size_t)ex * CAP * KD;
    const float* B    = Ball    + (size_t)ex * KD * ND;
    const float* bias = biasAll + (size_t)ex * ND;
    float*       C    = (GELU ? g_h : g_o) + (size_t)ex * CAP * ND;

    const int m0 = blockIdx.y * 128;
    const int n0 = blockIdx.x * 128;
    const int tid = threadIdx.x;

    const int rowA = tid >> 1, segA = (tid & 1) * 4;      // A tile 128x8
    const int rowB = tid >> 5, colB = (tid & 31) * 4;     // B tile 8x128

    const float* aptr = A + (size_t)(m0 + rowA) * KD + segA;
    const float* bptr = B + (size_t)rowB * ND + n0 + colB;

    float4 aF = *(const float4*)aptr;
    float4 bF = *(const float4*)bptr;
    As[0][segA + 0][rowA] = aF.x;
    As[0][segA + 1][rowA] = aF.y;
    As[0][segA + 2][rowA] = aF.z;
    As[0][segA + 3][rowA] = aF.w;
    *(float4*)&Bs[0][rowB][colB] = bF;
    __syncthreads();

    float acc[8][8];
#pragma unroll
    for (int i = 0; i < 8; i++)
#pragma unroll
        for (int j = 0; j < 8; j++) acc[i][j] = 0.f;

    const int ty = tid >> 4, tx = tid & 15;
    const int KT = KD / 8;
    int cur = 0;

    for (int kt = 0; kt < KT; kt++) {
        const bool pf = (kt + 1 < KT);
        if (pf) {
            aF = *(const float4*)(aptr + (size_t)(kt + 1) * 8);
            bF = *(const float4*)(bptr + (size_t)(kt + 1) * 8 * ND);
        }
#pragma unroll
        for (int k = 0; k < 8; k++) {
            float a[8], b[8];
            *(float4*)&a[0] = *(const float4*)&As[cur][k][ty * 8];
            *(float4*)&a[4] = *(const float4*)&As[cur][k][ty * 8 + 4];
            *(float4*)&b[0] = *(const float4*)&Bs[cur][k][tx * 8];
            *(float4*)&b[4] = *(const float4*)&Bs[cur][k][tx * 8 + 4];
#pragma unroll
            for (int i = 0; i < 8; i++)
#pragma unroll
                for (int j = 0; j < 8; j++) acc[i][j] += a[i] * b[j];
        }
        if (pf) {
            const int nx = cur ^ 1;
            As[nx][segA + 0][rowA] = aF.x;
            As[nx][segA + 1][rowA] = aF.y;
            As[nx][segA + 2][rowA] = aF.z;
            As[nx][segA + 3][rowA] = aF.w;
            *(float4*)&Bs[nx][rowB][colB] = bF;
        }
        __syncthreads();
        cur ^= 1;
    }

    float bv[8];
#pragma unroll
    for (int j = 0; j < 8; j++) bv[j] = bias[n0 + tx * 8 + j];
#pragma unroll
    for (int i = 0; i < 8; i++) {
        float out[8];
#pragma unroll
        for (int j = 0; j < 8; j++) {
            float v = acc[i][j] + bv[j];
            out[j] = GELU ? gelu_exact(v) : v;
        }
        float* crow = C + (size_t)(m0 + ty * 8 + i) * ND + n0 + tx * 8;
        *(float4*)(crow)     = *(float4*)&out[0];
        *(float4*)(crow + 4) = *(float4*)&out[4];
    }
}

// ---------------- combine: one block per token ------------------------------
__global__ void combine_kernel(float* __restrict__ y) {
    const int tok = blockIdx.x;
    const int e0 = g_exp [tok * 2],     e1 = g_exp [tok * 2 + 1];
    const int p0 = g_pos [tok * 2],     p1 = g_pos [tok * 2 + 1];
    const float gA = g_gate[tok * 2],   gB = g_gate[tok * 2 + 1];
    const bool k0 = p0 < CAP, k1 = p1 < CAP;
    const float ws  = (k0 ? gA : 0.f) + (k1 ? gB : 0.f);
    const float inv = (ws > 0.f) ? (1.f / fmaxf(ws, 1e-6f)) : 0.f;

    const float4* o0 = (const float4*)(g_o + ((size_t)e0 * CAP + p0) * DDIM);
    const float4* o1 = (const float4*)(g_o + ((size_t)e1 * CAP + p1) * DDIM);
    float4* yr = (float4*)(y + (size_t)tok * DDIM);

    const int i = threadIdx.x;   // D/4 = 256 == blockDim.x
    float4 r = make_float4(0.f, 0.f, 0.f, 0.f);
    if (k0) { float4 v = o0[i]; r.x += gA * v.x; r.y += gA * v.y; r.z += gA * v.z; r.w += gA * v.w; }
    if (k1) { float4 v = o1[i]; r.x += gB * v.x; r.y += gB * v.y; r.z += gB * v.z; r.w += gB * v.w; }
    r.x *= inv; r.y *= inv; r.z *= inv; r.w *= inv;
    yr[i] = r;
}

// ---------------- launch ----------------------------------------------------
extern "C" void kernel_launch(void* const* d_in, const int* in_sizes, int n_in,
                              void* d_out, int out_size) {
    const float* x  = (const float*)d_in[0];
    const float* wr = (const float*)d_in[1];
    const float* br = (const float*)d_in[2];
    const float* w1 = (const float*)d_in[3];
    const float* b1 = (const float*)d_in[4];
    const float* w2 = (const float*)d_in[5];
    const float* b2 = (const float*)d_in[6];
    float* y = (float*)d_out;

    router_kernel <<<NTOK / 8, 256>>>(x, wr, br);
    scan_kernel   <<<1, 1024>>>();
    dispatch_kernel<<<NK, 256>>>(x);
    gemm_kernel<DDIM, FDIM, true ><<<dim3(FDIM / 128, CAP / 128, NEXP), 256>>>(w1, b1);
    gemm_kernel<FDIM, DDIM, false><<<dim3(DDIM / 128, CAP / 128, NEXP), 256>>>(w2, b2);
    combine_kernel<<<NTOK, 256>>>(y);
}

// round 2
// speedup vs baseline: 2.8070x; 2.8070x over previous
#include <cuda_runtime.h>
#include <math.h>
#include <stdint.h>

// Problem dims (fixed for this dataset)
#define NTOK 16384        // B*T = 8*2048
#define DDIM 1024
#define NEXP 8
#define FDIM 4096
#define TOPK 2
#define NK   (NTOK*TOPK)  // 32768 assignments
#define CAP  2560         // int(1.25 * 16384 / 8)

// ---------------- scratch (device globals: allocation-free) ----------------
__device__ float g_buf[(size_t)NEXP * CAP * DDIM];   // dispatched tokens  [E,cap,D]
__device__ float g_h  [(size_t)NEXP * CAP * FDIM];   // hidden activations [E,cap,F]
__device__ float g_o  [(size_t)NEXP * CAP * DDIM];   // expert outputs     [E,cap,D]
__device__ int   g_exp [NK];
__device__ float g_gate[NK];
__device__ int   g_pos [NK];

// ---------------- router: warp per token -----------------------------------
__global__ void router_kernel(const float* __restrict__ x,
                              const float* __restrict__ wr,
                              const float* __restrict__ br) {
    int tok  = (blockIdx.x * blockDim.x + threadIdx.x) >> 5;
    int lane = threadIdx.x & 31;
    if (tok >= NTOK) return;
    const float* xr = x + (size_t)tok * DDIM;

    float acc[NEXP];
#pragma unroll
    for (int e = 0; e < NEXP; e++) acc[e] = 0.f;

    for (int c = lane * 4; c < DDIM; c += 128) {
        float4 xv = *(const float4*)(xr + c);
        float xs[4] = {xv.x, xv.y, xv.z, xv.w};
#pragma unroll
        for (int j = 0; j < 4; j++) {
            const float4* w = (const float4*)(wr + (size_t)(c + j) * NEXP);
            float4 w0 = w[0], w1 = w[1];
            acc[0] += xs[j] * w0.x; acc[1] += xs[j] * w0.y;
            acc[2] += xs[j] * w0.z; acc[3] += xs[j] * w0.w;
            acc[4] += xs[j] * w1.x; acc[5] += xs[j] * w1.y;
            acc[6] += xs[j] * w1.z; acc[7] += xs[j] * w1.w;
        }
    }
#pragma unroll
    for (int off = 16; off; off >>= 1) {
#pragma unroll
        for (int e = 0; e < NEXP; e++)
            acc[e] += __shfl_xor_sync(0xffffffffu, acc[e], off);
    }
    if (lane == 0) {
        float l[NEXP], mx = -1e30f;
#pragma unroll
        for (int e = 0; e < NEXP; e++) { l[e] = acc[e] + br[e]; mx = fmaxf(mx, l[e]); }
        float s = 0.f;
#pragma unroll
        for (int e = 0; e < NEXP; e++) { l[e] = expf(l[e] - mx); s += l[e]; }
        float inv = 1.f / s;
#pragma unroll
        for (int e = 0; e < NEXP; e++) l[e] *= inv;
        int i0 = 0; float v0 = l[0];
#pragma unroll
        for (int e = 1; e < NEXP; e++) if (l[e] > v0) { v0 = l[e]; i0 = e; }
        int i1 = -1; float v1 = -1.f;
#pragma unroll
        for (int e = 0; e < NEXP; e++) if (e != i0 && l[e] > v1) { v1 = l[e]; i1 = e; }
        g_exp [tok * 2]     = i0;  g_exp [tok * 2 + 1] = i1;
        g_gate[tok * 2]     = v0;  g_gate[tok * 2 + 1] = v1;
    }
}

// ---------------- exact arrival-order positions (single block) -------------
__global__ void scan_kernel() {
    __shared__ int s[NEXP][1024];
    const int t = threadIdx.x;
    const int base = t * 32;

    int cnt[NEXP];
#pragma unroll
    for (int e = 0; e < NEXP; e++) cnt[e] = 0;

    int le[32];
#pragma unroll
    for (int i = 0; i < 32; i++) { int e = g_exp[base + i]; le[i] = e; cnt[e]++; }

#pragma unroll
    for (int e = 0; e < NEXP; e++) s[e][t] = cnt[e];
    __syncthreads();

    for (int st = 1; st < 1024; st <<= 1) {
        int v[NEXP];
#pragma unroll
        for (int e = 0; e < NEXP; e++)
            v[e] = s[e][t] + (t >= st ? s[e][t - st] : 0);
        __syncthreads();
#pragma unroll
        for (int e = 0; e < NEXP; e++) s[e][t] = v[e];
        __syncthreads();
    }

    int run[NEXP];
#pragma unroll
    for (int e = 0; e < NEXP; e++) run[e] = (t > 0) ? s[e][t - 1] : 0;

#pragma unroll
    for (int i = 0; i < 32; i++) {
        int e = le[i];
        g_pos[base + i] = run[e]++;
    }
}

// ---------------- dispatch: one block per assignment ------------------------
__global__ void dispatch_kernel(const float* __restrict__ x) {
    const int a = blockIdx.x;
    const int p = g_pos[a];
    if (p >= CAP) return;
    const int e   = g_exp[a];
    const int tok = a >> 1;
    const float4* src = (const float4*)(x + (size_t)tok * DDIM);
    float4*       dst = (float4*)(g_buf + ((size_t)e * CAP + p) * DDIM);
    dst[threadIdx.x] = src[threadIdx.x];
}

// ---------------- tf32 tensor-core grouped GEMM -----------------------------
__device__ __forceinline__ float gelu_exact(float v) {
    return 0.5f * v * (1.f + erff(v * 0.70710678118654752440f));
}

__device__ __forceinline__ uint32_t f2tf(float f) {
    uint32_t u; asm("cvt.rna.tf32.f32 %0, %1;" : "=r"(u) : "f"(f)); return u;
}

// C[M,N] = act(A[M,K] @ B[K,N] + bias), A row-major, B row-major.
// Block tile 128x128, BK=16, 8 warps, warp tile 64x32 via mma.m16n8k8.tf32.
template<int KD, int ND, bool GELU>
__global__ void __launch_bounds__(256, 2)
mma_gemm_kernel(const float* __restrict__ Ball, const float* __restrict__ biasAll) {
    __shared__ uint32_t As[2][128][20];   // [m][k], pad 16->20 (frag loads conflict-free)
    __shared__ uint32_t Bs[2][16][136];   // [k][n], pad 128->136 (conflict-free)

    const int ex = blockIdx.z;
    const float* A    = (GELU ? g_buf : g_h) + (size_t)ex * CAP * KD;
    const float* B    = Ball    + (size_t)ex * KD * ND;
    const float* bias = biasAll + (size_t)ex * ND;
    float*       C    = (GELU ? g_h : g_o) + (size_t)ex * CAP * ND;

    const int m0 = blockIdx.y * 128;
    const int n0 = blockIdx.x * 128;
    const int tid  = threadIdx.x;
    const int warp = tid >> 5, lane = tid & 31;
    const int mw = (warp >> 2) * 64;      // warp M offset (0/64)
    const int nw = (warp & 3) * 32;       // warp N offset (0/32/64/96)
    const int r = lane >> 2, c = lane & 3;

    // global->smem mapping
    const int amRow = tid >> 2,  akq = (tid & 3) * 4;    // A: [128][16] as 512 float4
    const int bkRow = tid >> 5,  bnq = (tid & 31) * 4;   // B: [16][128] as 512 float4

    const float* aptr0 = A + (size_t)(m0 + amRow)      * KD + akq;
    const float* aptr1 = A + (size_t)(m0 + amRow + 64) * KD + akq;
    const float* bptr0 = B + (size_t)bkRow       * ND + n0 + bnq;
    const float* bptr1 = B + (size_t)(bkRow + 8) * ND + n0 + bnq;

    float4 fa0, fa1, fb0, fb1;

    // prologue: tile 0
    fa0 = *(const float4*)(aptr0);
    fa1 = *(const float4*)(aptr1);
    fb0 = *(const float4*)(bptr0);
    fb1 = *(const float4*)(bptr1);
    {
        As[0][amRow][akq+0] = f2tf(fa0.x); As[0][amRow][akq+1] = f2tf(fa0.y);
        As[0][amRow][akq+2] = f2tf(fa0.z); As[0][amRow][akq+3] = f2tf(fa0.w);
        As[0][amRow+64][akq+0] = f2tf(fa1.x); As[0][amRow+64][akq+1] = f2tf(fa1.y);
        As[0][amRow+64][akq+2] = f2tf(fa1.z); As[0][amRow+64][akq+3] = f2tf(fa1.w);
        Bs[0][bkRow][bnq+0] = f2tf(fb0.x); Bs[0][bkRow][bnq+1] = f2tf(fb0.y);
        Bs[0][bkRow][bnq+2] = f2tf(fb0.z); Bs[0][bkRow][bnq+3] = f2tf(fb0.w);
        Bs[0][bkRow+8][bnq+0] = f2tf(fb1.x); Bs[0][bkRow+8][bnq+1] = f2tf(fb1.y);
        Bs[0][bkRow+8][bnq+2] = f2tf(fb1.z); Bs[0][bkRow+8][bnq+3] = f2tf(fb1.w);
    }
    __syncthreads();

    float acc[4][4][4];
#pragma unroll
    for (int i = 0; i < 4; i++)
#pragma unroll
        for (int j = 0; j < 4; j++)
#pragma unroll
            for (int q = 0; q < 4; q++) acc[i][j][q] = 0.f;

    const int KT = KD / 16;
    int cur = 0;

    for (int kt = 0; kt < KT; kt++) {
        const bool pf = (kt + 1 < KT);
        if (pf) {
            fa0 = *(const float4*)(aptr0 + (size_t)(kt + 1) * 16);
            fa1 = *(const float4*)(aptr1 + (size_t)(kt + 1) * 16);
            fb0 = *(const float4*)(bptr0 + (size_t)(kt + 1) * 16 * ND);
            fb1 = *(const float4*)(bptr1 + (size_t)(kt + 1) * 16 * ND);
        }

#pragma unroll
        for (int kk = 0; kk < 16; kk += 8) {
            uint32_t af[4][4], bf[4][2];
#pragma unroll
            for (int mt = 0; mt < 4; mt++) {
                const int mrow = mw + mt * 16 + r;
                af[mt][0] = As[cur][mrow    ][kk + c];
                af[mt][1] = As[cur][mrow + 8][kk + c];
                af[mt][2] = As[cur][mrow    ][kk + c + 4];
                af[mt][3] = As[cur][mrow + 8][kk + c + 4];
            }
#pragma unroll
            for (int nt = 0; nt < 4; nt++) {
                const int ncol = nw + nt * 8 + r;
                bf[nt][0] = Bs[cur][kk + c    ][ncol];
                bf[nt][1] = Bs[cur][kk + c + 4][ncol];
            }
#pragma unroll
            for (int mt = 0; mt < 4; mt++)
#pragma unroll
                for (int nt = 0; nt < 4; nt++) {
                    asm volatile(
                        "mma.sync.aligned.m16n8k8.row.col.f32.tf32.tf32.f32 "
                        "{%0,%1,%2,%3}, {%4,%5,%6,%7}, {%8,%9}, {%0,%1,%2,%3};"
                        : "+f"(acc[mt][nt][0]), "+f"(acc[mt][nt][1]),
                          "+f"(acc[mt][nt][2]), "+f"(acc[mt][nt][3])
                        : "r"(af[mt][0]), "r"(af[mt][1]), "r"(af[mt][2]), "r"(af[mt][3]),
                          "r"(bf[nt][0]), "r"(bf[nt][1]));
                }
        }

        if (pf) {
            const int nx = cur ^ 1;
            As[nx][amRow][akq+0] = f2tf(fa0.x); As[nx][amRow][akq+1] = f2tf(fa0.y);
            As[nx][amRow][akq+2] = f2tf(fa0.z); As[nx][amRow][akq+3] = f2tf(fa0.w);
            As[nx][amRow+64][akq+0] = f2tf(fa1.x); As[nx][amRow+64][akq+1] = f2tf(fa1.y);
            As[nx][amRow+64][akq+2] = f2tf(fa1.z); As[nx][amRow+64][akq+3] = f2tf(fa1.w);
            Bs[nx][bkRow][bnq+0] = f2tf(fb0.x); Bs[nx][bkRow][bnq+1] = f2tf(fb0.y);
            Bs[nx][bkRow][bnq+2] = f2tf(fb0.z); Bs[nx][bkRow][bnq+3] = f2tf(fb0.w);
            Bs[nx][bkRow+8][bnq+0] = f2tf(fb1.x); Bs[nx][bkRow+8][bnq+1] = f2tf(fb1.y);
            Bs[nx][bkRow+8][bnq+2] = f2tf(fb1.z); Bs[nx][bkRow+8][bnq+3] = f2tf(fb1.w);
        }
        __syncthreads();
        cur ^= 1;
    }

    // epilogue: bias + (optional) GELU, float2 stores
#pragma unroll
    for (int mt = 0; mt < 4; mt++) {
        const int row = m0 + mw + mt * 16 + r;
#pragma unroll
        for (int nt = 0; nt < 4; nt++) {
            const int col = n0 + nw + nt * 8 + 2 * c;
            const float b0v = bias[col], b1v = bias[col + 1];
            float v0 = acc[mt][nt][0] + b0v;
            float v1 = acc[mt][nt][1] + b1v;
            float v2 = acc[mt][nt][2] + b0v;
            float v3 = acc[mt][nt][3] + b1v;
            if (GELU) {
                v0 = gelu_exact(v0); v1 = gelu_exact(v1);
                v2 = gelu_exact(v2); v3 = gelu_exact(v3);
            }
            *(float2*)(C + (size_t)row * ND + col)       = make_float2(v0, v1);
            *(float2*)(C + (size_t)(row + 8) * ND + col) = make_float2(v2, v3);
        }
    }
}

// ---------------- combine: one block per token ------------------------------
__global__ void combine_kernel(float* __restrict__ y) {
    const int tok = blockIdx.x;
    const int e0 = g_exp [tok * 2],     e1 = g_exp [tok * 2 + 1];
    const int p0 = g_pos [tok * 2],     p1 = g_pos [tok * 2 + 1];
    const float gA = g_gate[tok * 2],   gB = g_gate[tok * 2 + 1];
    const bool k0 = p0 < CAP, k1 = p1 < CAP;
    const float ws  = (k0 ? gA : 0.f) + (k1 ? gB : 0.f);
    const float inv = (ws > 0.f) ? (1.f / fmaxf(ws, 1e-6f)) : 0.f;

    const float4* o0 = (const float4*)(g_o + ((size_t)e0 * CAP + p0) * DDIM);
    const float4* o1 = (const float4*)(g_o + ((size_t)e1 * CAP + p1) * DDIM);
    float4* yr = (float4*)(y + (size_t)tok * DDIM);

    const int i = threadIdx.x;
    float4 rv = make_float4(0.f, 0.f, 0.f, 0.f);
    if (k0) { float4 v = o0[i]; rv.x += gA * v.x; rv.y += gA * v.y; rv.z += gA * v.z; rv.w += gA * v.w; }
    if (k1) { float4 v = o1[i]; rv.x += gB * v.x; rv.y += gB * v.y; rv.z += gB * v.z; rv.w += gB * v.w; }
    rv.x *= inv; rv.y *= inv; rv.z *= inv; rv.w *= inv;
    yr[i] = rv;
}

// ---------------- launch ----------------------------------------------------
extern "C" void kernel_launch(void* const* d_in, const int* in_sizes, int n_in,
                              void* d_out, int out_size) {
    const float* x  = (const float*)d_in[0];
    const float* wr = (const float*)d_in[1];
    const float* br = (const float*)d_in[2];
    const float* w1 = (const float*)d_in[3];
    const float* b1 = (const float*)d_in[4];
    const float* w2 = (const float*)d_in[5];
    const float* b2 = (const float*)d_in[6];
    float* y = (float*)d_out;

    router_kernel  <<<NTOK / 8, 256>>>(x, wr, br);
    scan_kernel    <<<1, 1024>>>();
    dispatch_kernel<<<NK, 256>>>(x);
    mma_gemm_kernel<DDIM, FDIM, true ><<<dim3(FDIM / 128, CAP / 128, NEXP), 256>>>(w1, b1);
    mma_gemm_kernel<FDIM, DDIM, false><<<dim3(DDIM / 128, CAP / 128, NEXP), 256>>>(w2, b2);
    combine_kernel <<<NTOK, 256>>>(y);
}

// round 4
// speedup vs baseline: 2.9040x; 1.0345x over previous
#include <cuda_runtime.h>
#include <math.h>
#include <stdint.h>

// Problem dims (fixed for this dataset)
#define NTOK 16384
#define DDIM 1024
#define NEXP 8
#define FDIM 4096
#define TOPK 2
#define NK   (NTOK*TOPK)
#define CAP  2560

// ---------------- scratch (device globals: allocation-free) ----------------
__device__ __align__(16) float g_buf [(size_t)NEXP * CAP * DDIM];   // [E,cap,D] tf32-rounded
__device__ __align__(16) float g_h   [(size_t)NEXP * CAP * FDIM];   // [E,cap,F] tf32-rounded
__device__ __align__(16) float g_o   [(size_t)NEXP * CAP * DDIM];   // [E,cap,D]
__device__ __align__(16) float g_w1r [(size_t)NEXP * DDIM * FDIM];  // tf32-rounded w1
__device__ __align__(16) float g_w2r [(size_t)NEXP * FDIM * DDIM];  // tf32-rounded w2
__device__ int   g_exp [NK];
__device__ float g_gate[NK];
__device__ int   g_pos [NK];

__device__ __forceinline__ uint32_t f2tf(float f) {
    uint32_t u; asm("cvt.rna.tf32.f32 %0, %1;" : "=r"(u) : "f"(f)); return u;
}
__device__ __forceinline__ uint32_t smem_u32(const void* p) {
    uint32_t a;
    asm("{ .reg .u64 t; cvta.to.shared.u64 t, %1; cvt.u32.u64 %0, t; }" : "=r"(a) : "l"(p));
    return a;
}
__device__ __forceinline__ void cp_async16(uint32_t dst, const float* src) {
    asm volatile("cp.async.cg.shared.global [%0], [%1], 16;" :: "r"(dst), "l"(src) : "memory");
}
#define CP_COMMIT() asm volatile("cp.async.commit_group;" ::: "memory")
#define CP_WAIT(n)  asm volatile("cp.async.wait_group %0;" :: "n"(n) : "memory")

// ---------------- router: warp per token -----------------------------------
__global__ void router_kernel(const float* __restrict__ x,
                              const float* __restrict__ wr,
                              const float* __restrict__ br) {
    int tok  = (blockIdx.x * blockDim.x + threadIdx.x) >> 5;
    int lane = threadIdx.x & 31;
    if (tok >= NTOK) return;
    const float* xr = x + (size_t)tok * DDIM;

    float acc[NEXP];
#pragma unroll
    for (int e = 0; e < NEXP; e++) acc[e] = 0.f;
    for (int c = lane * 4; c < DDIM; c += 128) {
        float4 xv = *(const float4*)(xr + c);
        float xs[4] = {xv.x, xv.y, xv.z, xv.w};
#pragma unroll
        for (int j = 0; j < 4; j++) {
            const float4* w = (const float4*)(wr + (size_t)(c + j) * NEXP);
            float4 w0 = w[0], w1 = w[1];
            acc[0] += xs[j] * w0.x; acc[1] += xs[j] * w0.y;
            acc[2] += xs[j] * w0.z; acc[3] += xs[j] * w0.w;
            acc[4] += xs[j] * w1.x; acc[5] += xs[j] * w1.y;
            acc[6] += xs[j] * w1.z; acc[7] += xs[j] * w1.w;
        }
    }
#pragma unroll
    for (int off = 16; off; off >>= 1)
#pragma unroll
        for (int e = 0; e < NEXP; e++)
            acc[e] += __shfl_xor_sync(0xffffffffu, acc[e], off);
    if (lane == 0) {
        float l[NEXP], mx = -1e30f;
#pragma unroll
        for (int e = 0; e < NEXP; e++) { l[e] = acc[e] + br[e]; mx = fmaxf(mx, l[e]); }
        float s = 0.f;
#pragma unroll
        for (int e = 0; e < NEXP; e++) { l[e] = expf(l[e] - mx); s += l[e]; }
        float inv = 1.f / s;
#pragma unroll
        for (int e = 0; e < NEXP; e++) l[e] *= inv;
        int i0 = 0; float v0 = l[0];
#pragma unroll
        for (int e = 1; e < NEXP; e++) if (l[e] > v0) { v0 = l[e]; i0 = e; }
        int i1 = -1; float v1 = -1.f;
#pragma unroll
        for (int e = 0; e < NEXP; e++) if (e != i0 && l[e] > v1) { v1 = l[e]; i1 = e; }
        g_exp [tok * 2] = i0;  g_exp [tok * 2 + 1] = i1;
        g_gate[tok * 2] = v0;  g_gate[tok * 2 + 1] = v1;
    }
}

// ---------------- exact arrival-order positions -----------------------------
__global__ void scan_kernel() {
    __shared__ int s[NEXP][1024];
    const int t = threadIdx.x;
    const int base = t * 32;
    int cnt[NEXP];
#pragma unroll
    for (int e = 0; e < NEXP; e++) cnt[e] = 0;
    int le[32];
#pragma unroll
    for (int i = 0; i < 32; i++) { int e = g_exp[base + i]; le[i] = e; cnt[e]++; }
#pragma unroll
    for (int e = 0; e < NEXP; e++) s[e][t] = cnt[e];
    __syncthreads();
    for (int st = 1; st < 1024; st <<= 1) {
        int v[NEXP];
#pragma unroll
        for (int e = 0; e < NEXP; e++) v[e] = s[e][t] + (t >= st ? s[e][t - st] : 0);
        __syncthreads();
#pragma unroll
        for (int e = 0; e < NEXP; e++) s[e][t] = v[e];
        __syncthreads();
    }
    int run[NEXP];
#pragma unroll
    for (int e = 0; e < NEXP; e++) run[e] = (t > 0) ? s[e][t - 1] : 0;
#pragma unroll
    for (int i = 0; i < 32; i++) { int e = le[i]; g_pos[base + i] = run[e]++; }
}

// ---------------- dispatch (stores tf32-rounded) ----------------------------
__global__ void dispatch_kernel(const float* __restrict__ x) {
    const int a = blockIdx.x;
    const int p = g_pos[a];
    if (p >= CAP) return;
    const int e   = g_exp[a];
    const int tok = a >> 1;
    const float4* src = (const float4*)(x + (size_t)tok * DDIM);
    uint4*        dst = (uint4*)(g_buf + ((size_t)e * CAP + p) * DDIM);
    float4 v = src[threadIdx.x];
    uint4 o; o.x = f2tf(v.x); o.y = f2tf(v.y); o.z = f2tf(v.z); o.w = f2tf(v.w);
    dst[threadIdx.x] = o;
}

// ---------------- weight tf32 pre-round -------------------------------------
__global__ void round_w_kernel(const float* __restrict__ s, float* __restrict__ d) {
    const int i = blockIdx.x * blockDim.x + threadIdx.x;   // n4 chunks of float4
    float4 v = ((const float4*)s)[i];
    uint4 o; o.x = f2tf(v.x); o.y = f2tf(v.y); o.z = f2tf(v.z); o.w = f2tf(v.w);
    ((uint4*)d)[i] = o;
}

// ---------------- HMMA tf32 grouped GEMM, cp.async 3-stage -------------------
__device__ __forceinline__ float gelu_exact(float v) {
    return 0.5f * v * (1.f + erff(v * 0.70710678118654752440f));
}

// CTA tile 128x256, BK=16, 8 warps (2M x 4N) of 64x64.
// As stage: [128][20] floats (pad conflict-free).  Bs stage: [16][264].
#define AST_F   (128 * 20)           // 2560 floats
#define BST_F   (16 * 264)           // 4224 floats
#define STG_F   (AST_F + BST_F)      // 6784 floats
#define NSTG    3
#define SMEM_BYTES (NSTG * STG_F * 4)  // 81408

template<int KD, int NDC, bool GELU>
__global__ void __launch_bounds__(256, 1)
mma_gemm_kernel(const float* __restrict__ Ball, const float* __restrict__ biasAll) {
    extern __shared__ float sm[];
    const uint32_t sb = smem_u32(sm);

    const int ex = blockIdx.z;
    const int m0 = blockIdx.y * 128;
    const int n0 = blockIdx.x * 256;
    const float* A    = (GELU ? g_buf : g_h) + (size_t)ex * CAP * KD + (size_t)m0 * KD;
    const float* B    = Ball + (size_t)ex * KD * NDC + n0;
    const float* bias = biasAll + (size_t)ex * NDC;
    float*       C    = (GELU ? g_h : g_o) + (size_t)ex * CAP * NDC;

    const int tid  = threadIdx.x;
    const int warp = tid >> 5, lane = tid & 31;
    const int mw  = (warp >> 2) * 64;     // 0 / 64
    const int nww = (warp & 3) * 64;      // 0 / 64 / 128 / 192
    const int r = lane >> 2, c = lane & 3;

    // cp.async source/dest mapping (per thread, per stage)
    const int arow = tid >> 2,  akq = (tid & 3) * 4;     // A chunks: tid, tid+256
    const float* srcA0 = A + (size_t)arow * KD + akq;
    const float* srcA1 = A + (size_t)(arow + 64) * KD + akq;
    const uint32_t dA0 = (uint32_t)(arow * 20 + akq) * 4u;
    const uint32_t dA1 = (uint32_t)((arow + 64) * 20 + akq) * 4u;
    // B chunks: tid + i*256, i=0..3 ; krow = ch>>6, nq = ch&63
    uint32_t dB[4]; const float* srcB[4];
#pragma unroll
    for (int i = 0; i < 4; i++) {
        const int ch = tid + i * 256;
        const int krow = ch >> 6, nq = ch & 63;
        srcB[i] = B + (size_t)krow * NDC + nq * 4;
        dB[i]   = (uint32_t)(AST_F + krow * 264 + nq * 4) * 4u;
    }

    constexpr int KT = KD / 16;

    // prologue: stages 0,1
#pragma unroll
    for (int s = 0; s < 2; s++) {
        const uint32_t sg = sb + (uint32_t)(s * STG_F) * 4u;
        cp_async16(sg + dA0, srcA0 + s * 16);
        cp_async16(sg + dA1, srcA1 + s * 16);
#pragma unroll
        for (int i = 0; i < 4; i++)
            cp_async16(sg + dB[i], srcB[i] + (size_t)s * 16 * NDC);
        CP_COMMIT();
    }

    float acc[4][8][4];
#pragma unroll
    for (int i = 0; i < 4; i++)
#pragma unroll
        for (int j = 0; j < 8; j++)
#pragma unroll
            for (int q = 0; q < 4; q++) acc[i][j][q] = 0.f;

    for (int kt = 0; kt < KT; kt++) {
        if (kt < KT - 1) CP_WAIT(1); else CP_WAIT(0);
        __syncthreads();

        if (kt + 2 < KT) {
            const int s = kt + 2;
            const uint32_t sg = sb + (uint32_t)((s % NSTG) * STG_F) * 4u;
            cp_async16(sg + dA0, srcA0 + (size_t)s * 16);
            cp_async16(sg + dA1, srcA1 + (size_t)s * 16);
#pragma unroll
            for (int i = 0; i < 4; i++)
                cp_async16(sg + dB[i], srcB[i] + (size_t)s * 16 * NDC);
            CP_COMMIT();
        }

        const float* as = sm + (kt % NSTG) * STG_F;
        const float* bs = as + AST_F;

#pragma unroll
        for (int kk = 0; kk < 16; kk += 8) {
            uint32_t af[4][4], bf[8][2];
#pragma unroll
            for (int mt = 0; mt < 4; mt++) {
                const int mrow = mw + mt * 16 + r;
                af[mt][0] = __float_as_uint(as[(mrow    ) * 20 + kk + c    ]);
                af[mt][1] = __float_as_uint(as[(mrow + 8) * 20 + kk + c    ]);
                af[mt][2] = __float_as_uint(as[(mrow    ) * 20 + kk + c + 4]);
                af[mt][3] = __float_as_uint(as[(mrow + 8) * 20 + kk + c + 4]);
            }
#pragma unroll
            for (int nt = 0; nt < 8; nt++) {
                const int ncol = nww + nt * 8 + r;
                bf[nt][0] = __float_as_uint(bs[(kk + c    ) * 264 + ncol]);
                bf[nt][1] = __float_as_uint(bs[(kk + c + 4) * 264 + ncol]);
            }
#pragma unroll
            for (int mt = 0; mt < 4; mt++)
#pragma unroll
                for (int nt = 0; nt < 8; nt++) {
                    asm volatile(
                        "mma.sync.aligned.m16n8k8.row.col.f32.tf32.tf32.f32 "
                        "{%0,%1,%2,%3}, {%4,%5,%6,%7}, {%8,%9}, {%0,%1,%2,%3};"
                        : "+f"(acc[mt][nt][0]), "+f"(acc[mt][nt][1]),
                          "+f"(acc[mt][nt][2]), "+f"(acc[mt][nt][3])
                        : "r"(af[mt][0]), "r"(af[mt][1]), "r"(af[mt][2]), "r"(af[mt][3]),
                          "r"(bf[nt][0]), "r"(bf[nt][1]));
                }
        }
        __syncthreads();
    }

    // epilogue: bias + optional GELU (+tf32 round for next GEMM's A)
    float bv[8][2];
#pragma unroll
    for (int nt = 0; nt < 8; nt++) {
        const int col = n0 + nww + nt * 8 + 2 * c;
        bv[nt][0] = bias[col]; bv[nt][1] = bias[col + 1];
    }
#pragma unroll
    for (int mt = 0; mt < 4; mt++) {
        const int row = m0 + mw + mt * 16 + r;
#pragma unroll
        for (int nt = 0; nt < 8; nt++) {
            const int col = n0 + nww + nt * 8 + 2 * c;
            float v0 = acc[mt][nt][0] + bv[nt][0];
            float v1 = acc[mt][nt][1] + bv[nt][1];
            float v2 = acc[mt][nt][2] + bv[nt][0];
            float v3 = acc[mt][nt][3] + bv[nt][1];
            if (GELU) {
                v0 = __uint_as_float(f2tf(gelu_exact(v0)));
                v1 = __uint_as_float(f2tf(gelu_exact(v1)));
                v2 = __uint_as_float(f2tf(gelu_exact(v2)));
                v3 = __uint_as_float(f2tf(gelu_exact(v3)));
            }
            *(float2*)(C + (size_t)row * NDC + col)       = make_float2(v0, v1);
            *(float2*)(C + (size_t)(row + 8) * NDC + col) = make_float2(v2, v3);
        }
    }
}

// ---------------- combine ---------------------------------------------------
__global__ void combine_kernel(float* __restrict__ y) {
    const int tok = blockIdx.x;
    const int e0 = g_exp [tok * 2],     e1 = g_exp [tok * 2 + 1];
    const int p0 = g_pos [tok * 2],     p1 = g_pos [tok * 2 + 1];
    const float gA = g_gate[tok * 2],   gB = g_gate[tok * 2 + 1];
    const bool k0 = p0 < CAP, k1 = p1 < CAP;
    const float ws  = (k0 ? gA : 0.f) + (k1 ? gB : 0.f);
    const float inv = (ws > 0.f) ? (1.f / fmaxf(ws, 1e-6f)) : 0.f;
    const float4* o0 = (const float4*)(g_o + ((size_t)e0 * CAP + p0) * DDIM);
    const float4* o1 = (const float4*)(g_o + ((size_t)e1 * CAP + p1) * DDIM);
    float4* yr = (float4*)(y + (size_t)tok * DDIM);
    const int i = threadIdx.x;
    float4 rv = make_float4(0.f, 0.f, 0.f, 0.f);
    if (k0) { float4 v = o0[i]; rv.x += gA * v.x; rv.y += gA * v.y; rv.z += gA * v.z; rv.w += gA * v.w; }
    if (k1) { float4 v = o1[i]; rv.x += gB * v.x; rv.y += gB * v.y; rv.z += gB * v.z; rv.w += gB * v.w; }
    rv.x *= inv; rv.y *= inv; rv.z *= inv; rv.w *= inv;
    yr[i] = rv;
}

// ---------------- launch ----------------------------------------------------
extern "C" void kernel_launch(void* const* d_in, const int* in_sizes, int n_in,
                              void* d_out, int out_size) {
    const float* x  = (const float*)d_in[0];
    const float* wr = (const float*)d_in[1];
    const float* br = (const float*)d_in[2];
    const float* w1 = (const float*)d_in[3];
    const float* b1 = (const float*)d_in[4];
    const float* w2 = (const float*)d_in[5];
    const float* b2 = (const float*)d_in[6];
    float* y = (float*)d_out;

    void *pW1r, *pW2r;
    cudaGetSymbolAddress(&pW1r, g_w1r);
    cudaGetSymbolAddress(&pW2r, g_w2r);

    cudaFuncSetAttribute(mma_gemm_kernel<DDIM, FDIM, true >,
                         cudaFuncAttributeMaxDynamicSharedMemorySize, SMEM_BYTES);
    cudaFuncSetAttribute(mma_gemm_kernel<FDIM, DDIM, false>,
                         cudaFuncAttributeMaxDynamicSharedMemorySize, SMEM_BYTES);

    const int n4 = NEXP * DDIM * FDIM / 4;  // 8M float4 chunks per weight tensor
    round_w_kernel<<<n4 / 256, 256>>>(w1, (float*)pW1r);
    round_w_kernel<<<n4 / 256, 256>>>(w2, (float*)pW2r);
    router_kernel  <<<NTOK / 8, 256>>>(x, wr, br);
    scan_kernel    <<<1, 1024>>>();
    dispatch_kernel<<<NK, 256>>>(x);
    mma_gemm_kernel<DDIM, FDIM, true ><<<dim3(FDIM / 256, CAP / 128, NEXP), 256, SMEM_BYTES>>>((const float*)pW1r, b1);
    mma_gemm_kernel<FDIM, DDIM, false><<<dim3(DDIM / 256, CAP / 128, NEXP), 256, SMEM_BYTES>>>((const float*)pW2r, b2);
    combine_kernel <<<NTOK, 256>>>(y);
}